// round 2
// baseline (speedup 1.0000x reference)
#include <cuda_runtime.h>
#include <cuda_bf16.h>
#include <cstdint>

// ---------------------------------------------------------------------------
// SpatialNonIntersectionAxiom: pairwise segment proximity loss over E edges.
// Outputs (loss scalar, violation_mask ExE, violation_scores ExE) flattened
// as float32: out[0]=loss, out[1..1+E^2)=mask, out[1+E^2..1+2E^2)=scores.
// ---------------------------------------------------------------------------

#define MAXE 8192
#define BLK  256
#define TI   4   // i-rows per block
#define TJ   4   // j's per thread (strided by BLK for coalesced stores)

// Per-edge precomputed data (scratch: __device__ globals, no allocs allowed)
__device__ float4 g_eA[MAXE];  // p_src.x, p_src.y, d1.x, d1.y
__device__ float4 g_eB[MAXE];  // mid.x, mid.y, half, sq (clamped)
__device__ float4 g_eC[MAXE];  // d1·p_src, batch(bits), src(bits), dst(bits)

// Spread-address reduction accumulators (fixed-point 2^-40 for determinism)
__device__ unsigned long long g_rowAcc[MAXE / TI + 1];
__device__ unsigned long long g_rowCnt[MAXE / TI + 1];

__global__ void prep_kernel(const float* __restrict__ pos,
                            const int* __restrict__ ei,   // int32 edge indices
                            int E, int N, int nodes, int nrows) {
    int e = blockIdx.x * blockDim.x + threadIdx.x;
    if (e < nrows) { g_rowAcc[e] = 0ull; g_rowCnt[e] = 0ull; }
    if (e >= E) return;
    int s = ei[e];
    int d = ei[E + e];
    // Defensive clamp: if dtype/layout assumption is off we produce wrong
    // values (visible as rel_err) instead of an illegal access.
    s = min(max(s, 0), nodes - 1);
    d = min(max(d, 0), nodes - 1);
    float psx = pos[2 * s],  psy = pos[2 * s + 1];
    float pdx = pos[2 * d],  pdy = pos[2 * d + 1];
    float d1x = pdx - psx,   d1y = pdy - psy;
    float rawsq = d1x * d1x + d1y * d1y;
    float sq    = fmaxf(rawsq, 1e-12f);
    float half  = __fsqrt_rn(rawsq) * 0.5f;
    float midx  = (psx + pdx) * 0.5f;
    float midy  = (psy + pdy) * 0.5f;
    float dda   = d1x * psx + d1y * psy;
    int   b     = s / N;
    g_eA[e] = make_float4(psx, psy, d1x, d1y);
    g_eB[e] = make_float4(midx, midy, half, sq);
    g_eC[e] = make_float4(dda, __int_as_float(b),
                          __int_as_float(s), __int_as_float(d));
}

__global__ void __launch_bounds__(BLK)
pair_kernel(float* __restrict__ out, int E, int writeBig) {
    const int i0    = blockIdx.y * TI;
    const int jbase = blockIdx.x * (BLK * TJ) + threadIdx.x;

    // Preload TI rows of i-edge data (warp-uniform -> broadcast L1 hits)
    float4 iA[TI], iB[TI], iC[TI];
#pragma unroll
    for (int a = 0; a < TI; a++) {
        int i = i0 + a;
        int ic = (i < E) ? i : (E - 1);
        iA[a] = g_eA[ic]; iB[a] = g_eB[ic]; iC[a] = g_eC[ic];
    }

    float* __restrict__ outMask  = out + 1;
    float* __restrict__ outScore = out + 1 + (size_t)E * (size_t)E;

    unsigned long long accQ = 0ull;
    unsigned int       cnt  = 0u;

#pragma unroll
    for (int jj = 0; jj < TJ; jj++) {
        int j = jbase + jj * BLK;
        if (j >= E) continue;
        float4 jA = g_eA[j], jB = g_eB[j], jC = g_eC[j];
        int bj = __float_as_int(jC.y);
        int sj = __float_as_int(jC.z);
        int dj = __float_as_int(jC.w);
#pragma unroll
        for (int a = 0; a < TI; a++) {
            int i = i0 + a;
            if (i >= E) continue;
            float pl = 0.0f;
            if (j > i && __float_as_int(iC[a].y) == bj) {
                int si = __float_as_int(iC[a].z);
                int di = __float_as_int(iC[a].w);
                bool shares = (si == sj) | (si == dj) | (di == sj) | (di == dj);
                if (!shares) {
                    float dx = iB[a].x - jB.x;
                    float dy = iB[a].y - jB.y;
                    float dist  = __fsqrt_rn(dx * dx + dy * dy);
                    float reach = iB[a].z + jB.z + 0.15f;
                    if (dist < reach) {
                        cnt++;  // n_pairs counts the candidate mask
                        // Segment-segment min distance (matches reference order)
                        float A  = iB[a].w;        // sq_i (clamped)
                        float Ee = jB.w;           // sq_j (clamped)
                        float b  = iA[a].z * jA.z + iA[a].w * jA.w;
                        float c  = iC[a].x - (iA[a].z * jA.x + iA[a].w * jA.y);
                        float f  = (iA[a].x * jA.z + iA[a].y * jA.w) - jC.x;
                        float denom = fmaxf(A * Ee - b * b, 1e-12f);
                        float s = __fdiv_rn(b * f - c * Ee, denom);
                        s = fminf(fmaxf(s, 0.0f), 1.0f);
                        float t = fminf(fmaxf(__fdiv_rn(b * s + f, Ee), 0.0f), 1.0f);
                        s = fminf(fmaxf(__fdiv_rn(b * t - c, A), 0.0f), 1.0f);
                        float cax = iA[a].x + s * iA[a].z;
                        float cay = iA[a].y + s * iA[a].w;
                        float cbx = jA.x + t * jA.z;
                        float cby = jA.y + t * jA.w;
                        float ddx = cax - cbx;
                        float ddy = cay - cby;
                        float dmin = __fsqrt_rn(ddx * ddx + ddy * ddy);
                        pl = fmaxf(0.001f - dmin, 0.0f);
                        if (pl > 0.0f) {
                            // fixed-point 2^40 accumulation: deterministic sum
                            accQ += (unsigned long long)
                                __double2ll_rn((double)pl * 1099511627776.0);
                        }
                    }
                }
            }
            if (writeBig) {
                size_t off = (size_t)i * (size_t)E + (size_t)j;
                outMask[off]  = (pl > 0.0f) ? 1.0f : 0.0f;  // mask & (pair_loss > 0)
                outScore[off] = pl;                          // pair_loss
            }
        }
    }

    // Block reduction -> spread-address atomics (one row-block per address)
#pragma unroll
    for (int o = 16; o; o >>= 1) {
        accQ += __shfl_xor_sync(0xffffffffu, accQ, o);
        cnt  += __shfl_xor_sync(0xffffffffu, cnt,  o);
    }
    __shared__ unsigned long long sQ[BLK / 32];
    __shared__ unsigned int       sC[BLK / 32];
    int w = threadIdx.x >> 5;
    if ((threadIdx.x & 31) == 0) { sQ[w] = accQ; sC[w] = cnt; }
    __syncthreads();
    if (threadIdx.x == 0) {
        unsigned long long q = 0ull; unsigned int c = 0u;
#pragma unroll
        for (int k = 0; k < BLK / 32; k++) { q += sQ[k]; c += sC[k]; }
        if (q | (unsigned long long)c) {
            atomicAdd(&g_rowAcc[blockIdx.y], q);
            atomicAdd(&g_rowCnt[blockIdx.y], (unsigned long long)c);
        }
    }
}

__global__ void finalize_kernel(float* __restrict__ out, int nrows) {
    __shared__ unsigned long long sQ[256];
    __shared__ unsigned long long sC[256];
    unsigned long long q = 0ull, c = 0ull;
    for (int k = threadIdx.x; k < nrows; k += 256) {
        q += g_rowAcc[k];
        c += g_rowCnt[k];
    }
    sQ[threadIdx.x] = q; sC[threadIdx.x] = c;
    __syncthreads();
    for (int st = 128; st; st >>= 1) {
        if (threadIdx.x < st) {
            sQ[threadIdx.x] += sQ[threadIdx.x + st];
            sC[threadIdx.x] += sC[threadIdx.x + st];
        }
        __syncthreads();
    }
    if (threadIdx.x == 0) {
        double sum = (double)sQ[0] * (1.0 / 1099511627776.0);
        unsigned long long n = sC[0] ? sC[0] : 1ull;
        out[0] = (float)(sum / (double)n);
    }
}

extern "C" void kernel_launch(void* const* d_in, const int* in_sizes, int n_in,
                              void* d_out, int out_size) {
    const float* pos = (const float*)d_in[0];
    // d_in[1] = adjacency: unused by the reference computation
    const int*   ei  = (const int*)d_in[2];   // int32 (jax x64 disabled)

    int E     = in_sizes[2] / 2;              // edge count
    int nodes = in_sizes[0] / 2;              // B*N
    int N     = in_sizes[1] / nodes;          // B*N*N / (B*N)
    int nrows = (E + TI - 1) / TI;

    // Guard the big ExE writes against an unexpected output layout:
    // produce wrong values (diagnosable) instead of an illegal access.
    long long need = 1ll + 2ll * (long long)E * (long long)E;
    int writeBig = ((long long)out_size >= need) ? 1 : 0;

    float* out = (float*)d_out;

    prep_kernel<<<(E + 255) / 256, 256>>>(pos, ei, E, N, nodes, nrows);

    dim3 grid((E + BLK * TJ - 1) / (BLK * TJ), nrows);
    pair_kernel<<<grid, BLK>>>(out, E, writeBig);

    finalize_kernel<<<1, 256>>>(out, nrows);
}